// round 2
// baseline (speedup 1.0000x reference)
#include <cuda_runtime.h>
#include <cuda_bf16.h>
#include <cstdint>
#include <cmath>

#define B_  4
#define L_  4096
#define H_  2048
#define I_  5504
#define BL  16384           // B_*L_
#define I2  11008           // 2*I_
#define K1T 192             // (3*H_)/32  k-tiles gemm1
#define K2T 516             // (3*I_)/32  k-tiles gemm2

// ---------------- scratch (device globals; no allocation allowed) ----------------
__device__ __nv_bfloat16 g_h_hi[(size_t)BL * H_];
__device__ __nv_bfloat16 g_h_lo[(size_t)BL * H_];
__device__ __nv_bfloat16 g_act_hi[(size_t)BL * I_];
__device__ __nv_bfloat16 g_act_lo[(size_t)BL * I_];
__device__ __nv_bfloat16 g_wgu_hi[(size_t)H_ * I2];
__device__ __nv_bfloat16 g_wgu_lo[(size_t)H_ * I2];
__device__ __nv_bfloat16 g_wd_hi[(size_t)I_ * H_];
__device__ __nv_bfloat16 g_wd_lo[(size_t)I_ * H_];
__device__ int g_idx[BL];
__device__ int g_count;

// ---------------- helpers ----------------
__device__ __forceinline__ uint32_t smem_u32(const void* p) {
    return (uint32_t)__cvta_generic_to_shared(p);
}

__device__ __forceinline__ void ldmA(uint32_t* r, uint32_t addr) {
    asm volatile("ldmatrix.sync.aligned.m8n8.x4.shared.b16 {%0,%1,%2,%3}, [%4];"
                 : "=r"(r[0]), "=r"(r[1]), "=r"(r[2]), "=r"(r[3]) : "r"(addr));
}
__device__ __forceinline__ void ldmB(uint32_t* r, uint32_t addr) {
    asm volatile("ldmatrix.sync.aligned.m8n8.x2.trans.shared.b16 {%0,%1}, [%2];"
                 : "=r"(r[0]), "=r"(r[1]) : "r"(addr));
}
__device__ __forceinline__ void mma16816(float* c, const uint32_t* a, const uint32_t* b) {
    asm volatile("mma.sync.aligned.m16n8k16.row.col.f32.bf16.bf16.f32 "
                 "{%0,%1,%2,%3}, {%4,%5,%6,%7}, {%8,%9}, {%0,%1,%2,%3};"
                 : "+f"(c[0]), "+f"(c[1]), "+f"(c[2]), "+f"(c[3])
                 : "r"(a[0]), "r"(a[1]), "r"(a[2]), "r"(a[3]), "r"(b[0]), "r"(b[1]));
}
__device__ __forceinline__ void bf16_split(float x, __nv_bfloat16& h, __nv_bfloat16& l) {
    h = __float2bfloat16(x);
    l = __float2bfloat16(x - __bfloat162float(h));
}

// ---------------- kernel 1: zero output + reset counter ----------------
__global__ void k_zero(float* __restrict__ out, size_t n4) {
    size_t i = (size_t)blockIdx.x * blockDim.x + threadIdx.x;
    size_t stride = (size_t)gridDim.x * blockDim.x;
    float4 z = make_float4(0.f, 0.f, 0.f, 0.f);
    float4* o4 = reinterpret_cast<float4*>(out);
    for (; i < n4; i += stride) o4[i] = z;
    if (blockIdx.x == 0 && threadIdx.x == 0) g_count = 0;
}

// ---------------- kernel 2: split+interleave gate/up weights ----------------
// wgu[k][2j] = gate_w[k][j], wgu[k][2j+1] = up_w[k][j]  (hi/lo bf16 split)
__global__ void k_conv_gu(const float* __restrict__ gw, const float* __restrict__ uw) {
    const int n = H_ * I_;
    for (int id = blockIdx.x * blockDim.x + threadIdx.x; id < n;
         id += gridDim.x * blockDim.x) {
        int k = id / I_;
        int j = id - k * I_;
        float g = gw[id], u = uw[id];
        __nv_bfloat16 gh, gl, uh, ul;
        bf16_split(g, gh, gl);
        bf16_split(u, uh, ul);
        size_t o = (size_t)k * I2 + 2 * j;
        *reinterpret_cast<__nv_bfloat162*>(g_wgu_hi + o) = __halves2bfloat162(gh, uh);
        *reinterpret_cast<__nv_bfloat162*>(g_wgu_lo + o) = __halves2bfloat162(gl, ul);
    }
}

// ---------------- kernel 3: split down weights ----------------
__global__ void k_conv_down(const float* __restrict__ dw) {
    const int n = I_ * H_;
    for (int id = blockIdx.x * blockDim.x + threadIdx.x; id < n;
         id += gridDim.x * blockDim.x) {
        __nv_bfloat16 h, l;
        bf16_split(dw[id], h, l);
        g_wd_hi[id] = h;
        g_wd_lo[id] = l;
    }
}

// ---------------- kernel 4: RMSNorm + mask compaction ----------------
// NOTE: sparse_mask is a bool array in JAX; the harness materializes it as
// int32 (one int per token). Reading it as bytes was the round-1 bug.
__global__ void k_rmsnorm(const float* __restrict__ x,
                          const int* __restrict__ mask,
                          const float* __restrict__ lnw) {
    int token = blockIdx.x;
    int tid = threadIdx.x;
    const float4* row = reinterpret_cast<const float4*>(x + (size_t)token * H_);
    float4 v[2];
    float ss = 0.f;
#pragma unroll
    for (int i = 0; i < 2; i++) {
        float4 t = row[tid + i * 256];
        v[i] = t;
        ss += t.x * t.x + t.y * t.y + t.z * t.z + t.w * t.w;
    }
#pragma unroll
    for (int o = 16; o > 0; o >>= 1) ss += __shfl_xor_sync(0xffffffffu, ss, o);

    __shared__ float warpsum[8];
    __shared__ float s_rs;
    __shared__ int s_slot;
    if ((tid & 31) == 0) warpsum[tid >> 5] = ss;
    __syncthreads();
    if (tid == 0) {
        float tot = 0.f;
#pragma unroll
        for (int w = 0; w < 8; w++) tot += warpsum[w];
        s_rs = rsqrtf(tot * (1.0f / H_) + 1e-6f);
        s_slot = (mask[token] != 0) ? atomicAdd(&g_count, 1) : -1;
    }
    __syncthreads();
    int slot = s_slot;
    if (slot < 0) return;
    float rs = s_rs;
    if (tid == 0) g_idx[slot] = token;

    const float4* lw4 = reinterpret_cast<const float4*>(lnw);
#pragma unroll
    for (int i = 0; i < 2; i++) {
        int c4 = tid + i * 256;
        float4 w = lw4[c4];
        float h0 = v[i].x * rs * w.x, h1 = v[i].y * rs * w.y;
        float h2 = v[i].z * rs * w.z, h3 = v[i].w * rs * w.w;
        __nv_bfloat16 a0, b0, a1, b1, a2, b2, a3, b3;
        bf16_split(h0, a0, b0);
        bf16_split(h1, a1, b1);
        bf16_split(h2, a2, b2);
        bf16_split(h3, a3, b3);
        size_t o = (size_t)slot * H_ + (size_t)c4 * 4;
        __nv_bfloat162* ph = reinterpret_cast<__nv_bfloat162*>(g_h_hi + o);
        __nv_bfloat162* pl = reinterpret_cast<__nv_bfloat162*>(g_h_lo + o);
        ph[0] = __halves2bfloat162(a0, a1);
        ph[1] = __halves2bfloat162(a2, a3);
        pl[0] = __halves2bfloat162(b0, b1);
        pl[1] = __halves2bfloat162(b2, b3);
    }
}

// ---------------- GEMM common tile config ----------------
#define TM 128
#define TN 128
#define TK 32
#define ASTRIDE 40    // bf16 elems per smem A row (pad; 80B, 16B-multiple)
#define BSTRIDE 136   // bf16 elems per smem B row (pad; 272B, 16B-multiple)

// ---------------- kernel 5: GEMM1  h[M,2048] x wgu[2048,11008] (3x split K) ----------------
// epilogue: act = silu(g + gate_b) * (u + up_b) -> bf16 hi/lo split, compacted rows
__global__ __launch_bounds__(256, 2) void k_gemm1(const float* __restrict__ gate_b,
                                                  const float* __restrict__ up_b) {
    int cnt = g_count;
    int m_base = blockIdx.y * TM;
    if (m_base >= cnt) return;
    int n_base = blockIdx.x * TN;

    __shared__ __align__(16) __nv_bfloat16 As[TM * ASTRIDE];
    __shared__ __align__(16) __nv_bfloat16 Bs[TK * BSTRIDE];

    int tid = threadIdx.x;
    int lane = tid & 31, warp = tid >> 5;
    int wm = warp >> 2, wn = warp & 3;   // 2x4 warp grid, warp tile 64x32

    float c[4][4][4];
#pragma unroll
    for (int mf = 0; mf < 4; mf++)
#pragma unroll
        for (int nf = 0; nf < 4; nf++)
#pragma unroll
            for (int i = 0; i < 4; i++) c[mf][nf][i] = 0.f;

    for (int kt = 0; kt < K1T; kt++) {
        int blk = kt >> 6;                       // /64: which K-block (0,1,2)
        int srck = (kt - (blk << 6)) * TK;       // k offset inside block [0,2048)
        const __nv_bfloat16* Asrc = (blk == 1) ? g_h_lo : g_h_hi;     // [hi, lo, hi]
        const __nv_bfloat16* Bsrc = (blk == 2) ? g_wgu_lo : g_wgu_hi; // [hi, hi, lo]

        __syncthreads();
#pragma unroll
        for (int i = 0; i < 4; i++) {            // A: 128x32 = 1024 uint2
            int idx = tid + i * 256;
            int r = idx >> 3, cc = (idx & 7) * 4;
            uint2 val = *reinterpret_cast<const uint2*>(
                Asrc + (size_t)(m_base + r) * H_ + srck + cc);
            *reinterpret_cast<uint2*>(&As[r * ASTRIDE + cc]) = val;
        }
#pragma unroll
        for (int i = 0; i < 2; i++) {            // B: 32x128 = 512 uint4
            int idx = tid + i * 256;
            int r = idx >> 4, cc = (idx & 15) * 8;
            uint4 val = *reinterpret_cast<const uint4*>(
                Bsrc + (size_t)(srck + r) * I2 + n_base + cc);
            *reinterpret_cast<uint4*>(&Bs[r * BSTRIDE + cc]) = val;
        }
        __syncthreads();

#pragma unroll
        for (int ks = 0; ks < 2; ks++) {
            uint32_t a[4][4], b[4][2];
#pragma unroll
            for (int mf = 0; mf < 4; mf++) {
                int row = wm * 64 + mf * 16 + (lane & 15);
                int col = ks * 16 + (lane >> 4) * 8;
                ldmA(a[mf], smem_u32(&As[row * ASTRIDE + col]));
            }
#pragma unroll
            for (int nf = 0; nf < 4; nf++) {
                int kk = ks * 16 + (lane & 15);
                int col = wn * 32 + nf * 8;
                ldmB(b[nf], smem_u32(&Bs[kk * BSTRIDE + col]));
            }
#pragma unroll
            for (int mf = 0; mf < 4; mf++)
#pragma unroll
                for (int nf = 0; nf < 4; nf++) mma16816(c[mf][nf], a[mf], b[nf]);
        }
    }

    // epilogue: each thread's (c0,c1)/(c2,c3) pairs = adjacent cols = (gate, up) for one j
#pragma unroll
    for (int mf = 0; mf < 4; mf++) {
        int row0 = m_base + wm * 64 + mf * 16 + (lane >> 2);
#pragma unroll
        for (int nf = 0; nf < 4; nf++) {
            int ncol = n_base + wn * 32 + nf * 8 + (lane & 3) * 2;
            int j = ncol >> 1;
            float bg = gate_b[j], bu = up_b[j];
#pragma unroll
            for (int rr = 0; rr < 2; rr++) {
                int row = row0 + rr * 8;
                if (row < cnt) {
                    float gg = c[mf][nf][rr * 2 + 0] + bg;
                    float uu = c[mf][nf][rr * 2 + 1] + bu;
                    float act = gg / (1.f + expf(-gg)) * uu;   // silu(g)*u
                    __nv_bfloat16 ah, al;
                    bf16_split(act, ah, al);
                    size_t o = (size_t)row * I_ + j;
                    g_act_hi[o] = ah;
                    g_act_lo[o] = al;
                }
            }
        }
    }
}

// ---------------- kernel 6: GEMM2  act[M,5504] x wd[5504,2048] (3x split K) ----------------
// epilogue: out[idx[m]][n] = acc + down_b[n]
__global__ __launch_bounds__(256, 2) void k_gemm2(const float* __restrict__ down_b,
                                                  float* __restrict__ out) {
    int cnt = g_count;
    int m_base = blockIdx.y * TM;
    if (m_base >= cnt) return;
    int n_base = blockIdx.x * TN;

    __shared__ __align__(16) __nv_bfloat16 As[TM * ASTRIDE];
    __shared__ __align__(16) __nv_bfloat16 Bs[TK * BSTRIDE];

    int tid = threadIdx.x;
    int lane = tid & 31, warp = tid >> 5;
    int wm = warp >> 2, wn = warp & 3;

    float c[4][4][4];
#pragma unroll
    for (int mf = 0; mf < 4; mf++)
#pragma unroll
        for (int nf = 0; nf < 4; nf++)
#pragma unroll
            for (int i = 0; i < 4; i++) c[mf][nf][i] = 0.f;

    for (int kt = 0; kt < K2T; kt++) {
        int blk = kt / 172;                      // 172*32 = 5504
        int srck = (kt - blk * 172) * TK;
        const __nv_bfloat16* Asrc = (blk == 1) ? g_act_lo : g_act_hi;  // [hi, lo, hi]
        const __nv_bfloat16* Bsrc = (blk == 2) ? g_wd_lo : g_wd_hi;    // [hi, hi, lo]

        __syncthreads();
#pragma unroll
        for (int i = 0; i < 4; i++) {
            int idx = tid + i * 256;
            int r = idx >> 3, cc = (idx & 7) * 4;
            uint2 val = *reinterpret_cast<const uint2*>(
                Asrc + (size_t)(m_base + r) * I_ + srck + cc);
            *reinterpret_cast<uint2*>(&As[r * ASTRIDE + cc]) = val;
        }
#pragma unroll
        for (int i = 0; i < 2; i++) {
            int idx = tid + i * 256;
            int r = idx >> 4, cc = (idx & 15) * 8;
            uint4 val = *reinterpret_cast<const uint4*>(
                Bsrc + (size_t)(srck + r) * H_ + n_base + cc);
            *reinterpret_cast<uint4*>(&Bs[r * BSTRIDE + cc]) = val;
        }
        __syncthreads();

#pragma unroll
        for (int ks = 0; ks < 2; ks++) {
            uint32_t a[4][4], b[4][2];
#pragma unroll
            for (int mf = 0; mf < 4; mf++) {
                int row = wm * 64 + mf * 16 + (lane & 15);
                int col = ks * 16 + (lane >> 4) * 8;
                ldmA(a[mf], smem_u32(&As[row * ASTRIDE + col]));
            }
#pragma unroll
            for (int nf = 0; nf < 4; nf++) {
                int kk = ks * 16 + (lane & 15);
                int col = wn * 32 + nf * 8;
                ldmB(b[nf], smem_u32(&Bs[kk * BSTRIDE + col]));
            }
#pragma unroll
            for (int mf = 0; mf < 4; mf++)
#pragma unroll
                for (int nf = 0; nf < 4; nf++) mma16816(c[mf][nf], a[mf], b[nf]);
        }
    }

#pragma unroll
    for (int mf = 0; mf < 4; mf++) {
        int row0 = m_base + wm * 64 + mf * 16 + (lane >> 2);
#pragma unroll
        for (int nf = 0; nf < 4; nf++) {
            int ncol = n_base + wn * 32 + nf * 8 + (lane & 3) * 2;
            float b0 = down_b[ncol], b1 = down_b[ncol + 1];
#pragma unroll
            for (int rr = 0; rr < 2; rr++) {
                int row = row0 + rr * 8;
                if (row < cnt) {
                    int token = g_idx[row];
                    float2 v = make_float2(c[mf][nf][rr * 2 + 0] + b0,
                                           c[mf][nf][rr * 2 + 1] + b1);
                    *reinterpret_cast<float2*>(out + (size_t)token * H_ + ncol) = v;
                }
            }
        }
    }
}

// ---------------- launch ----------------
extern "C" void kernel_launch(void* const* d_in, const int* in_sizes, int n_in,
                              void* d_out, int out_size) {
    (void)in_sizes; (void)n_in; (void)out_size;
    const float* x          = (const float*)d_in[0];
    const int* mk           = (const int*)d_in[1];
    const float* lnw        = (const float*)d_in[2];
    const float* gw         = (const float*)d_in[3];
    const float* gb         = (const float*)d_in[4];
    const float* uw         = (const float*)d_in[5];
    const float* ub         = (const float*)d_in[6];
    const float* dw         = (const float*)d_in[7];
    const float* db         = (const float*)d_in[8];
    float* out = (float*)d_out;

    k_zero<<<4096, 256>>>(out, (size_t)BL * H_ / 4);
    k_conv_gu<<<8192, 256>>>(gw, uw);
    k_conv_down<<<8192, 256>>>(dw);
    k_rmsnorm<<<BL, 256>>>(x, mk, lnw);
    k_gemm1<<<dim3(I2 / TN, BL / TM), 256>>>(gb, ub);
    k_gemm2<<<dim3(H_ / TN, BL / TM), 256>>>(db, out);
}

// round 4
// speedup vs baseline: 2.5376x; 2.5376x over previous
#include <cuda_runtime.h>
#include <cuda_fp16.h>
#include <cstdint>

#define B_  4
#define L_  4096
#define H_  2048
#define I_  5504
#define BL  16384           // B_*L_
#define I2  11008           // 2*I_

// ---------------- scratch (device globals; no allocation allowed) ----------------
__device__ __align__(256) __half g_h_hi[(size_t)BL * H_];     // [slot][H_] fp16 hi
__device__ __align__(256) __half g_h_lo[(size_t)BL * H_];     // fp16 lo (x - hi)
__device__ __align__(256) __half g_act_hi[(size_t)BL * I_];   // [slot][I_]
__device__ __align__(256) __half g_act_lo[(size_t)BL * I_];
__device__ __align__(256) __half g_wgu[(size_t)I2 * H_];      // [n][k], n interleaved (gate,up)
__device__ __align__(256) __half g_wd[(size_t)H_ * I_];       // [n=h][k=i]
__device__ int g_idx[BL];
__device__ int g_count;

// ---------------- helpers ----------------
__device__ __forceinline__ uint32_t smem_u32(const void* p) {
    return (uint32_t)__cvta_generic_to_shared(p);
}
#define SWZ128(off) ((off) ^ (((off) >> 3) & 0x70))

__device__ __forceinline__ void ldmA4(uint32_t* r, uint32_t addr) {
    asm volatile("ldmatrix.sync.aligned.m8n8.x4.shared.b16 {%0,%1,%2,%3}, [%4];"
                 : "=r"(r[0]), "=r"(r[1]), "=r"(r[2]), "=r"(r[3]) : "r"(addr));
}
__device__ __forceinline__ void ldmB4(uint32_t* r, uint32_t addr) {
    asm volatile("ldmatrix.sync.aligned.m8n8.x4.shared.b16 {%0,%1,%2,%3}, [%4];"
                 : "=r"(r[0]), "=r"(r[1]), "=r"(r[2]), "=r"(r[3]) : "r"(addr));
}
__device__ __forceinline__ void mma_f16(float* c, const uint32_t* a, const uint32_t* b) {
    asm volatile("mma.sync.aligned.m16n8k16.row.col.f32.f16.f16.f32 "
                 "{%0,%1,%2,%3}, {%4,%5,%6,%7}, {%8,%9}, {%0,%1,%2,%3};"
                 : "+f"(c[0]), "+f"(c[1]), "+f"(c[2]), "+f"(c[3])
                 : "r"(a[0]), "r"(a[1]), "r"(a[2]), "r"(a[3]), "r"(b[0]), "r"(b[1]));
}
__device__ __forceinline__ void h16_split(float x, __half& h, __half& l) {
    h = __float2half(x);
    l = __float2half(x - __half2float(h));
}

// ---------------- kernel: zero output + reset counter ----------------
__global__ void k_zero(float* __restrict__ out, size_t n4) {
    size_t i = (size_t)blockIdx.x * blockDim.x + threadIdx.x;
    size_t stride = (size_t)gridDim.x * blockDim.x;
    float4 z = make_float4(0.f, 0.f, 0.f, 0.f);
    float4* o4 = reinterpret_cast<float4*>(out);
    for (; i < n4; i += stride) o4[i] = z;
    if (blockIdx.x == 0 && threadIdx.x == 0) g_count = 0;
}

// ---------------- conversion: transpose gate/up -> wgu[n][k] fp16, n interleaved ----------------
__global__ void k_conv_gu(const float* __restrict__ gw, const float* __restrict__ uw) {
    __shared__ float sg[32][33], su[32][33];
    int bid = blockIdx.x;
    int kt0 = (bid & 63) << 5;        // 64 k-tiles over H_
    int jt0 = (bid >> 6) << 5;        // 172 j-tiles over I_
    int tid = threadIdx.x;
#pragma unroll
    for (int i = 0; i < 4; i++) {
        int idx = tid + (i << 8);
        int r = idx >> 5, c = idx & 31;
        size_t src = (size_t)(kt0 + r) * I_ + jt0 + c;
        sg[r][c] = gw[src];
        su[r][c] = uw[src];
    }
    __syncthreads();
#pragma unroll
    for (int i = 0; i < 4; i++) {
        int idx = tid + (i << 8);
        int jr = idx >> 5, kc = idx & 31;
        size_t og = (size_t)((jt0 + jr) << 1) * H_ + kt0 + kc;
        g_wgu[og]      = __float2half(sg[kc][jr]);
        g_wgu[og + H_] = __float2half(su[kc][jr]);
    }
}

// down_w [I_][H_] -> wd[n=h][k=i] fp16
__global__ void k_conv_down(const float* __restrict__ dw) {
    __shared__ float s[32][33];
    int bid = blockIdx.x;
    int ht0 = (bid & 63) << 5;
    int it0 = (bid >> 6) << 5;
    int tid = threadIdx.x;
#pragma unroll
    for (int i = 0; i < 4; i++) {
        int idx = tid + (i << 8);
        int r = idx >> 5, c = idx & 31;
        s[r][c] = dw[(size_t)(it0 + r) * H_ + ht0 + c];
    }
    __syncthreads();
#pragma unroll
    for (int i = 0; i < 4; i++) {
        int idx = tid + (i << 8);
        int hr = idx >> 5, ic = idx & 31;
        g_wd[(size_t)(ht0 + hr) * I_ + it0 + ic] = __float2half(s[ic][hr]);
    }
}

// ---------------- RMSNorm + mask compaction (mask is int32) ----------------
__global__ void k_rmsnorm(const float* __restrict__ x,
                          const int* __restrict__ mask,
                          const float* __restrict__ lnw) {
    int token = blockIdx.x;
    int tid = threadIdx.x;
    const float4* row = reinterpret_cast<const float4*>(x + (size_t)token * H_);
    float4 v[2];
    float ss = 0.f;
#pragma unroll
    for (int i = 0; i < 2; i++) {
        float4 t = row[tid + i * 256];
        v[i] = t;
        ss += t.x * t.x + t.y * t.y + t.z * t.z + t.w * t.w;
    }
#pragma unroll
    for (int o = 16; o > 0; o >>= 1) ss += __shfl_xor_sync(0xffffffffu, ss, o);

    __shared__ float warpsum[8];
    __shared__ float s_rs;
    __shared__ int s_slot;
    if ((tid & 31) == 0) warpsum[tid >> 5] = ss;
    __syncthreads();
    if (tid == 0) {
        float tot = 0.f;
#pragma unroll
        for (int w = 0; w < 8; w++) tot += warpsum[w];
        s_rs = rsqrtf(tot * (1.0f / H_) + 1e-6f);
        s_slot = (mask[token] != 0) ? atomicAdd(&g_count, 1) : -1;
    }
    __syncthreads();
    int slot = s_slot;
    if (slot < 0) return;
    float rs = s_rs;
    if (tid == 0) g_idx[slot] = token;

    const float4* lw4 = reinterpret_cast<const float4*>(lnw);
#pragma unroll
    for (int i = 0; i < 2; i++) {
        int c4 = tid + i * 256;
        float4 w = lw4[c4];
        float h0 = v[i].x * rs * w.x, h1 = v[i].y * rs * w.y;
        float h2 = v[i].z * rs * w.z, h3 = v[i].w * rs * w.w;
        __half a0, b0, a1, b1, a2, b2, a3, b3;
        h16_split(h0, a0, b0);
        h16_split(h1, a1, b1);
        h16_split(h2, a2, b2);
        h16_split(h3, a3, b3);
        size_t o = (size_t)slot * H_ + (size_t)c4 * 4;
        __half2* ph = reinterpret_cast<__half2*>(g_h_hi + o);
        __half2* pl = reinterpret_cast<__half2*>(g_h_lo + o);
        ph[0] = __halves2half2(a0, a1);
        ph[1] = __halves2half2(a2, a3);
        pl[0] = __halves2half2(b0, b1);
        pl[1] = __halves2half2(b2, b3);
    }
}

// ---------------- GEMM core: CTA 128x256, TK=64, 3-stage cp.async pipeline ----------------
// smem buffer (64KB): Ahi [128][64] @0, Alo [128][64] @16K, B [256][64] @32K. 3 bufs.
// A-split fp16 2-term: accum += Ahi*B then += Alo*B, B frags reused.
#define BUFSZ 65536
#define SMEM_SZ (3 * BUFSZ)

__device__ __forceinline__ void load_chunk(uint32_t smb, int buf,
    const __half* __restrict__ A0, const __half* __restrict__ A1, long ldA,
    const __half* __restrict__ Bp, long ldB, int k0, int tid)
{
    uint32_t sA0 = smb + buf * BUFSZ;
    uint32_t sA1 = sA0 + 16384;
    uint32_t sB  = sA0 + 32768;
#pragma unroll
    for (int i = 0; i < 4; i++) {
        int u = tid + (i << 8);
        int row = u >> 3, seg = u & 7;
        uint32_t soff = SWZ128((row << 7) + (seg << 4));
        const void* g0 = A0 + (long)row * ldA + k0 + (seg << 3);
        asm volatile("cp.async.cg.shared.global [%0], [%1], 16;"
                     :: "r"(sA0 + soff), "l"(g0));
        const void* g1 = A1 + (long)row * ldA + k0 + (seg << 3);
        asm volatile("cp.async.cg.shared.global [%0], [%1], 16;"
                     :: "r"(sA1 + soff), "l"(g1));
    }
#pragma unroll
    for (int i = 0; i < 8; i++) {
        int u = tid + (i << 8);
        int row = u >> 3, seg = u & 7;
        const void* g = Bp + (long)row * ldB + k0 + (seg << 3);
        asm volatile("cp.async.cg.shared.global [%0], [%1], 16;"
                     :: "r"(sB + SWZ128((row << 7) + (seg << 4))), "l"(g));
    }
}

__device__ __forceinline__ void compute_chunk(uint32_t smb, int buf,
    int wm, int wn, int lane, float c[4][8][4])
{
    uint32_t sA0 = smb + buf * BUFSZ;
    uint32_t sA1 = sA0 + 16384;
    uint32_t sB  = sA0 + 32768;
    int arow = wm * 64 + (lane & 15);
    int akh  = (lane >> 4) << 4;                     // 0/16 bytes
    int brow = wn * 64 + ((lane >> 4) << 3) + (lane & 7);
    int bkh  = ((lane >> 3) & 1) << 4;
#pragma unroll
    for (int ks = 0; ks < 4; ks++) {
        uint32_t a[4][4], b[8][2];
#pragma unroll
        for (int q = 0; q < 4; q++)
            ldmB4(&b[2 * q][0], sB + SWZ128(((brow + q * 16) << 7) + ks * 32 + bkh));
#pragma unroll
        for (int mf = 0; mf < 4; mf++)
            ldmA4(a[mf], sA0 + SWZ128(((arow + mf * 16) << 7) + ks * 32 + akh));
#pragma unroll
        for (int mf = 0; mf < 4; mf++)
#pragma unroll
            for (int q = 0; q < 8; q++) mma_f16(c[mf][q], a[mf], b[q]);
#pragma unroll
        for (int mf = 0; mf < 4; mf++)
            ldmA4(a[mf], sA1 + SWZ128(((arow + mf * 16) << 7) + ks * 32 + akh));
#pragma unroll
        for (int mf = 0; mf < 4; mf++)
#pragma unroll
            for (int q = 0; q < 8; q++) mma_f16(c[mf][q], a[mf], b[q]);
    }
}

__device__ __forceinline__ void gemm_main(uint32_t smb,
    const __half* A0, const __half* A1, long ldA,
    const __half* Bp, long ldB, int nch,
    float c[4][8][4], int tid, int wm, int wn, int lane)
{
    load_chunk(smb, 0, A0, A1, ldA, Bp, ldB, 0, tid);
    asm volatile("cp.async.commit_group;" ::: "memory");
    load_chunk(smb, 1, A0, A1, ldA, Bp, ldB, 64, tid);
    asm volatile("cp.async.commit_group;" ::: "memory");
    int ldbuf = 2, cbuf = 0;
#pragma unroll 1
    for (int ch = 0; ch < nch; ch++) {
        if (ch + 2 < nch)
            load_chunk(smb, ldbuf, A0, A1, ldA, Bp, ldB, (ch + 2) * 64, tid);
        asm volatile("cp.async.commit_group;" ::: "memory");
        asm volatile("cp.async.wait_group 2;" ::: "memory");
        __syncthreads();
        compute_chunk(smb, cbuf, wm, wn, lane, c);
        __syncthreads();
        if (++ldbuf == 3) ldbuf = 0;
        if (++cbuf == 3) cbuf = 0;
    }
}

// ---------------- GEMM1: h[M,2048] x wgu[11008,2048]^T, epilogue silu(g)*u ----------------
// grid: 8 m-supertiles x 43 n x 16 m  (m fastest for L2 reuse of B)
__global__ __launch_bounds__(256, 1) void k_gemm1(const float* __restrict__ gate_b,
                                                  const float* __restrict__ up_b) {
    extern __shared__ __align__(128) char sm[];
    int cnt = g_count;
    int bid = blockIdx.x;
    int mi = bid & 15, nt = (bid >> 4) % 43, ms = bid / 688;
    int m_base = (ms * 16 + mi) << 7;
    if (m_base >= cnt) return;
    int n_base = nt << 8;
    int tid = threadIdx.x, lane = tid & 31, w = tid >> 5, wm = w >> 2, wn = w & 3;

    float c[4][8][4];
#pragma unroll
    for (int mf = 0; mf < 4; mf++)
#pragma unroll
        for (int q = 0; q < 8; q++)
#pragma unroll
            for (int i = 0; i < 4; i++) c[mf][q][i] = 0.f;

    gemm_main(smem_u32(sm),
              g_h_hi + (size_t)m_base * H_, g_h_lo + (size_t)m_base * H_, H_,
              g_wgu + (size_t)n_base * H_, H_, H_ / 64, c, tid, wm, wn, lane);

    int jb = (n_base >> 1) + wn * 32 + (lane & 3);
    float bg[8], bu[8];
#pragma unroll
    for (int q = 0; q < 8; q++) { bg[q] = gate_b[jb + q * 4]; bu[q] = up_b[jb + q * 4]; }
#pragma unroll
    for (int mf = 0; mf < 4; mf++) {
#pragma unroll
        for (int rr = 0; rr < 2; rr++) {
            int row = m_base + wm * 64 + mf * 16 + (lane >> 2) + rr * 8;
            if (row < cnt) {
#pragma unroll
                for (int q = 0; q < 8; q++) {
                    float gg = c[mf][q][rr * 2 + 0] + bg[q];
                    float uu = c[mf][q][rr * 2 + 1] + bu[q];
                    float act = gg / (1.f + __expf(-gg)) * uu;
                    __half h, l;
                    h16_split(act, h, l);
                    size_t o = (size_t)row * I_ + jb + q * 4;
                    g_act_hi[o] = h;
                    g_act_lo[o] = l;
                }
            }
        }
    }
}

// ---------------- GEMM2: act[M,5504] x wd[2048,5504]^T, scatter + bias ----------------
// grid: 8 m-supertiles x 8 n x 16 m
__global__ __launch_bounds__(256, 1) void k_gemm2(const float* __restrict__ down_b,
                                                  float* __restrict__ out) {
    extern __shared__ __align__(128) char sm[];
    int cnt = g_count;
    int bid = blockIdx.x;
    int mi = bid & 15, nt = (bid >> 4) & 7, ms = bid >> 7;
    int m_base = (ms * 16 + mi) << 7;
    if (m_base >= cnt) return;
    int n_base = nt << 8;
    int tid = threadIdx.x, lane = tid & 31, w = tid >> 5, wm = w >> 2, wn = w & 3;

    float c[4][8][4];
#pragma unroll
    for (int mf = 0; mf < 4; mf++)
#pragma unroll
        for (int q = 0; q < 8; q++)
#pragma unroll
            for (int i = 0; i < 4; i++) c[mf][q][i] = 0.f;

    gemm_main(smem_u32(sm),
              g_act_hi + (size_t)m_base * I_, g_act_lo + (size_t)m_base * I_, I_,
              g_wd + (size_t)n_base * I_, I_, I_ / 64, c, tid, wm, wn, lane);

    int nb = n_base + wn * 64 + (lane & 3) * 2;
    float d0[8], d1[8];
#pragma unroll
    for (int q = 0; q < 8; q++) { d0[q] = down_b[nb + q * 8]; d1[q] = down_b[nb + q * 8 + 1]; }
#pragma unroll
    for (int mf = 0; mf < 4; mf++) {
#pragma unroll
        for (int rr = 0; rr < 2; rr++) {
            int row = m_base + wm * 64 + mf * 16 + (lane >> 2) + rr * 8;
            if (row < cnt) {
                int token = g_idx[row];
                float* orow = out + (size_t)token * H_;
#pragma unroll
                for (int q = 0; q < 8; q++) {
                    float2 v = make_float2(c[mf][q][rr * 2 + 0] + d0[q],
                                           c[mf][q][rr * 2 + 1] + d1[q]);
                    *reinterpret_cast<float2*>(orow + nb + q * 8) = v;
                }
            }
        }
    }
}

// ---------------- launch ----------------
extern "C" void kernel_launch(void* const* d_in, const int* in_sizes, int n_in,
                              void* d_out, int out_size) {
    (void)in_sizes; (void)n_in; (void)out_size;
    const float* x   = (const float*)d_in[0];
    const int* mk    = (const int*)d_in[1];
    const float* lnw = (const float*)d_in[2];
    const float* gw  = (const float*)d_in[3];
    const float* gb  = (const float*)d_in[4];
    const float* uw  = (const float*)d_in[5];
    const float* ub  = (const float*)d_in[6];
    const float* dw  = (const float*)d_in[7];
    const float* db  = (const float*)d_in[8];
    float* out = (float*)d_out;

    static bool attr_set = false;
    if (!attr_set) {
        cudaFuncSetAttribute(k_gemm1, cudaFuncAttributeMaxDynamicSharedMemorySize, SMEM_SZ);
        cudaFuncSetAttribute(k_gemm2, cudaFuncAttributeMaxDynamicSharedMemorySize, SMEM_SZ);
        attr_set = true;
    }

    k_zero<<<4096, 256>>>(out, (size_t)BL * H_ / 4);
    k_conv_gu<<<64 * 172, 256>>>(gw, uw);
    k_conv_down<<<64 * 172, 256>>>(dw);
    k_rmsnorm<<<BL, 256>>>(x, mk, lnw);
    k_gemm1<<<8 * 43 * 16, 256, SMEM_SZ>>>(gb, ub);
    k_gemm2<<<8 * 8 * 16, 256, SMEM_SZ>>>(db, out);
}

// round 5
// speedup vs baseline: 4.5169x; 1.7800x over previous
#include <cuda_runtime.h>
#include <cuda_fp16.h>
#include <cstdint>

#define B_  4
#define L_  4096
#define H_  2048
#define I_  5504
#define BL  16384           // B_*L_
#define I2  11008           // 2*I_

// ---------------- scratch (device globals; no allocation allowed) ----------------
__device__ __align__(256) __half g_h[(size_t)BL * H_];       // [slot][H_] fp16
__device__ __align__(256) __half g_act[(size_t)BL * I_];     // [slot][I_] fp16
__device__ __align__(256) __half g_wgu[(size_t)I2 * H_];     // [n][k], n interleaved (gate,up)
__device__ __align__(256) __half g_wd[(size_t)H_ * I_];      // [n=h][k=i]
__device__ int g_idx[BL];
__device__ int g_count;

// ---------------- helpers ----------------
__device__ __forceinline__ uint32_t smem_u32(const void* p) {
    return (uint32_t)__cvta_generic_to_shared(p);
}
#define SWZ128(off) ((off) ^ (((off) >> 3) & 0x70))

__device__ __forceinline__ void ldm4(uint32_t* r, uint32_t addr) {
    asm volatile("ldmatrix.sync.aligned.m8n8.x4.shared.b16 {%0,%1,%2,%3}, [%4];"
                 : "=r"(r[0]), "=r"(r[1]), "=r"(r[2]), "=r"(r[3]) : "r"(addr));
}
__device__ __forceinline__ void mma_f16(float* c, const uint32_t* a, const uint32_t* b) {
    asm volatile("mma.sync.aligned.m16n8k16.row.col.f32.f16.f16.f32 "
                 "{%0,%1,%2,%3}, {%4,%5,%6,%7}, {%8,%9}, {%0,%1,%2,%3};"
                 : "+f"(c[0]), "+f"(c[1]), "+f"(c[2]), "+f"(c[3])
                 : "r"(a[0]), "r"(a[1]), "r"(a[2]), "r"(a[3]), "r"(b[0]), "r"(b[1]));
}

// ---------------- kernel: zero output + reset counter ----------------
__global__ void k_zero(float* __restrict__ out, size_t n4) {
    size_t i = (size_t)blockIdx.x * blockDim.x + threadIdx.x;
    size_t stride = (size_t)gridDim.x * blockDim.x;
    float4 z = make_float4(0.f, 0.f, 0.f, 0.f);
    float4* o4 = reinterpret_cast<float4*>(out);
    for (; i < n4; i += stride) o4[i] = z;
    if (blockIdx.x == 0 && threadIdx.x == 0) g_count = 0;
}

// ---------------- conversion: transpose gate/up -> wgu[n][k] fp16, n interleaved ----------------
__global__ void k_conv_gu(const float* __restrict__ gw, const float* __restrict__ uw) {
    __shared__ float sg[32][33], su[32][33];
    int bid = blockIdx.x;
    int kt0 = (bid & 63) << 5;        // 64 k-tiles over H_
    int jt0 = (bid >> 6) << 5;        // 172 j-tiles over I_
    int tid = threadIdx.x;
#pragma unroll
    for (int i = 0; i < 4; i++) {
        int idx = tid + (i << 8);
        int r = idx >> 5, c = idx & 31;
        size_t src = (size_t)(kt0 + r) * I_ + jt0 + c;
        sg[r][c] = gw[src];
        su[r][c] = uw[src];
    }
    __syncthreads();
#pragma unroll
    for (int i = 0; i < 4; i++) {
        int idx = tid + (i << 8);
        int jr = idx >> 5, kc = idx & 31;
        size_t og = (size_t)((jt0 + jr) << 1) * H_ + kt0 + kc;
        g_wgu[og]      = __float2half(sg[kc][jr]);
        g_wgu[og + H_] = __float2half(su[kc][jr]);
    }
}

// down_w [I_][H_] -> wd[n=h][k=i] fp16
__global__ void k_conv_down(const float* __restrict__ dw) {
    __shared__ float s[32][33];
    int bid = blockIdx.x;
    int ht0 = (bid & 63) << 5;
    int it0 = (bid >> 6) << 5;
    int tid = threadIdx.x;
#pragma unroll
    for (int i = 0; i < 4; i++) {
        int idx = tid + (i << 8);
        int r = idx >> 5, c = idx & 31;
        s[r][c] = dw[(size_t)(it0 + r) * H_ + ht0 + c];
    }
    __syncthreads();
#pragma unroll
    for (int i = 0; i < 4; i++) {
        int idx = tid + (i << 8);
        int hr = idx >> 5, ic = idx & 31;
        g_wd[(size_t)(ht0 + hr) * I_ + it0 + ic] = __float2half(s[ic][hr]);
    }
}

// ---------------- RMSNorm + mask compaction (mask is int32) ----------------
__global__ void k_rmsnorm(const float* __restrict__ x,
                          const int* __restrict__ mask,
                          const float* __restrict__ lnw) {
    int token = blockIdx.x;
    if (mask[token] == 0) return;              // masked tokens: no work at all
    int tid = threadIdx.x;
    const float4* row = reinterpret_cast<const float4*>(x + (size_t)token * H_);
    float4 v[2];
    float ss = 0.f;
#pragma unroll
    for (int i = 0; i < 2; i++) {
        float4 t = row[tid + i * 256];
        v[i] = t;
        ss += t.x * t.x + t.y * t.y + t.z * t.z + t.w * t.w;
    }
#pragma unroll
    for (int o = 16; o > 0; o >>= 1) ss += __shfl_xor_sync(0xffffffffu, ss, o);

    __shared__ float warpsum[8];
    __shared__ float s_rs;
    __shared__ int s_slot;
    if ((tid & 31) == 0) warpsum[tid >> 5] = ss;
    __syncthreads();
    if (tid == 0) {
        float tot = 0.f;
#pragma unroll
        for (int w = 0; w < 8; w++) tot += warpsum[w];
        s_rs = rsqrtf(tot * (1.0f / H_) + 1e-6f);
        int slot = atomicAdd(&g_count, 1);
        s_slot = slot;
        g_idx[slot] = token;
    }
    __syncthreads();
    int slot = s_slot;
    float rs = s_rs;

    const float4* lw4 = reinterpret_cast<const float4*>(lnw);
#pragma unroll
    for (int i = 0; i < 2; i++) {
        int c4 = tid + i * 256;
        float4 w = lw4[c4];
        __half2* ph = reinterpret_cast<__half2*>(g_h + (size_t)slot * H_ + (size_t)c4 * 4);
        ph[0] = __halves2half2(__float2half(v[i].x * rs * w.x),
                               __float2half(v[i].y * rs * w.y));
        ph[1] = __halves2half2(__float2half(v[i].z * rs * w.z),
                               __float2half(v[i].w * rs * w.w));
    }
}

// ---------------- GEMM core: CTA 128x256, TK=64, 4-stage cp.async pipeline ----------------
// buffer (48KB): A [128][64] @0 (16KB), B [256][64] @16K (32KB). 4 buffers = 192KB.
#define BUFSZ 49152
#define NSTAGE 4
#define SMEM_SZ (NSTAGE * BUFSZ)

__device__ __forceinline__ void load_chunk(uint32_t smb, int buf,
    const __half* __restrict__ Ap, long ldA,
    const __half* __restrict__ Bp, long ldB, int k0, int tid)
{
    uint32_t sA = smb + buf * BUFSZ;
    uint32_t sB = sA + 16384;
#pragma unroll
    for (int i = 0; i < 4; i++) {               // A: 128 rows x 128B = 1024 x 16B
        int u = tid + (i << 8);
        int row = u >> 3, seg = u & 7;
        const void* g = Ap + (long)row * ldA + k0 + (seg << 3);
        asm volatile("cp.async.cg.shared.global [%0], [%1], 16;"
                     :: "r"(sA + SWZ128((row << 7) + (seg << 4))), "l"(g));
    }
#pragma unroll
    for (int i = 0; i < 8; i++) {               // B: 256 rows x 128B = 2048 x 16B
        int u = tid + (i << 8);
        int row = u >> 3, seg = u & 7;
        const void* g = Bp + (long)row * ldB + k0 + (seg << 3);
        asm volatile("cp.async.cg.shared.global [%0], [%1], 16;"
                     :: "r"(sB + SWZ128((row << 7) + (seg << 4))), "l"(g));
    }
}

__device__ __forceinline__ void compute_chunk(uint32_t smb, int buf,
    int wm, int wn, int lane, float c[4][8][4])
{
    uint32_t sA = smb + buf * BUFSZ;
    uint32_t sB = sA + 16384;
    int arow = wm * 64 + (lane & 15);
    int akh  = (lane >> 4) << 4;
    int brow = wn * 64 + ((lane >> 4) << 3) + (lane & 7);
    int bkh  = ((lane >> 3) & 1) << 4;
#pragma unroll
    for (int ks = 0; ks < 4; ks++) {
        uint32_t a[4][4], b[8][2];
#pragma unroll
        for (int q = 0; q < 4; q++)
            ldm4(&b[2 * q][0], sB + SWZ128(((brow + q * 16) << 7) + ks * 32 + bkh));
#pragma unroll
        for (int mf = 0; mf < 4; mf++)
            ldm4(a[mf], sA + SWZ128(((arow + mf * 16) << 7) + ks * 32 + akh));
#pragma unroll
        for (int mf = 0; mf < 4; mf++)
#pragma unroll
            for (int q = 0; q < 8; q++) mma_f16(c[mf][q], a[mf], b[q]);
    }
}

__device__ __forceinline__ void gemm_main(uint32_t smb,
    const __half* Ap, long ldA, const __half* Bp, long ldB, int nch,
    float c[4][8][4], int tid, int wm, int wn, int lane)
{
#pragma unroll
    for (int p = 0; p < NSTAGE - 1; p++) {
        load_chunk(smb, p, Ap, ldA, Bp, ldB, p * 64, tid);
        asm volatile("cp.async.commit_group;" ::: "memory");
    }
    int ldbuf = NSTAGE - 1, cbuf = 0;
#pragma unroll 1
    for (int ch = 0; ch < nch; ch++) {
        if (ch + NSTAGE - 1 < nch)
            load_chunk(smb, ldbuf, Ap, ldA, Bp, ldB, (ch + NSTAGE - 1) * 64, tid);
        asm volatile("cp.async.commit_group;" ::: "memory");
        asm volatile("cp.async.wait_group %0;" :: "n"(NSTAGE - 1) : "memory");
        __syncthreads();
        compute_chunk(smb, cbuf, wm, wn, lane, c);
        __syncthreads();
        if (++ldbuf == NSTAGE) ldbuf = 0;
        if (++cbuf == NSTAGE) cbuf = 0;
    }
}

// ---------------- GEMM1: h[M,2048] x wgu[11008,2048]^T, epilogue silu(g)*u ----------------
// grid: 8 m-supertiles x 43 n x 16 m  (m fastest for L2 reuse of B)
__global__ __launch_bounds__(256, 1) void k_gemm1(const float* __restrict__ gate_b,
                                                  const float* __restrict__ up_b) {
    extern __shared__ __align__(128) char sm[];
    int cnt = g_count;
    int bid = blockIdx.x;
    int mi = bid & 15, nt = (bid >> 4) % 43, ms = bid / 688;
    int m_base = (ms * 16 + mi) << 7;
    if (m_base >= cnt) return;
    int n_base = nt << 8;
    int tid = threadIdx.x, lane = tid & 31, w = tid >> 5, wm = w >> 2, wn = w & 3;

    float c[4][8][4];
#pragma unroll
    for (int mf = 0; mf < 4; mf++)
#pragma unroll
        for (int q = 0; q < 8; q++)
#pragma unroll
            for (int i = 0; i < 4; i++) c[mf][q][i] = 0.f;

    gemm_main(smem_u32(sm), g_h + (size_t)m_base * H_, H_,
              g_wgu + (size_t)n_base * H_, H_, H_ / 64, c, tid, wm, wn, lane);

    int jb = (n_base >> 1) + wn * 32 + (lane & 3);
    float bg[8], bu[8];
#pragma unroll
    for (int q = 0; q < 8; q++) { bg[q] = gate_b[jb + q * 4]; bu[q] = up_b[jb + q * 4]; }
#pragma unroll
    for (int mf = 0; mf < 4; mf++) {
#pragma unroll
        for (int rr = 0; rr < 2; rr++) {
            int row = m_base + wm * 64 + mf * 16 + (lane >> 2) + rr * 8;
            if (row < cnt) {
#pragma unroll
                for (int q = 0; q < 8; q++) {
                    float gg = c[mf][q][rr * 2 + 0] + bg[q];
                    float uu = c[mf][q][rr * 2 + 1] + bu[q];
                    float act = gg / (1.f + __expf(-gg)) * uu;
                    g_act[(size_t)row * I_ + jb + q * 4] = __float2half(act);
                }
            }
        }
    }
}

// ---------------- GEMM2: act[M,5504] x wd[2048,5504]^T, scatter + bias ----------------
// grid: 8 m-supertiles x 8 n x 16 m
__global__ __launch_bounds__(256, 1) void k_gemm2(const float* __restrict__ down_b,
                                                  float* __restrict__ out) {
    extern __shared__ __align__(128) char sm[];
    int cnt = g_count;
    int bid = blockIdx.x;
    int mi = bid & 15, nt = (bid >> 4) & 7, ms = bid >> 7;
    int m_base = (ms * 16 + mi) << 7;
    if (m_base >= cnt) return;
    int n_base = nt << 8;
    int tid = threadIdx.x, lane = tid & 31, w = tid >> 5, wm = w >> 2, wn = w & 3;

    float c[4][8][4];
#pragma unroll
    for (int mf = 0; mf < 4; mf++)
#pragma unroll
        for (int q = 0; q < 8; q++)
#pragma unroll
            for (int i = 0; i < 4; i++) c[mf][q][i] = 0.f;

    gemm_main(smem_u32(sm), g_act + (size_t)m_base * I_, I_,
              g_wd + (size_t)n_base * I_, I_, I_ / 64, c, tid, wm, wn, lane);

    int nb = n_base + wn * 64 + (lane & 3) * 2;
    float d0[8], d1[8];
#pragma unroll
    for (int q = 0; q < 8; q++) { d0[q] = down_b[nb + q * 8]; d1[q] = down_b[nb + q * 8 + 1]; }
#pragma unroll
    for (int mf = 0; mf < 4; mf++) {
#pragma unroll
        for (int rr = 0; rr < 2; rr++) {
            int row = m_base + wm * 64 + mf * 16 + (lane >> 2) + rr * 8;
            if (row < cnt) {
                int token = g_idx[row];
                float* orow = out + (size_t)token * H_;
#pragma unroll
                for (int q = 0; q < 8; q++) {
                    float2 v = make_float2(c[mf][q][rr * 2 + 0] + d0[q],
                                           c[mf][q][rr * 2 + 1] + d1[q]);
                    *reinterpret_cast<float2*>(orow + nb + q * 8) = v;
                }
            }
        }
    }
}

// ---------------- launch ----------------
extern "C" void kernel_launch(void* const* d_in, const int* in_sizes, int n_in,
                              void* d_out, int out_size) {
    (void)in_sizes; (void)n_in; (void)out_size;
    const float* x   = (const float*)d_in[0];
    const int* mk    = (const int*)d_in[1];
    const float* lnw = (const float*)d_in[2];
    const float* gw  = (const float*)d_in[3];
    const float* gb  = (const float*)d_in[4];
    const float* uw  = (const float*)d_in[5];
    const float* ub  = (const float*)d_in[6];
    const float* dw  = (const float*)d_in[7];
    const float* db  = (const float*)d_in[8];
    float* out = (float*)d_out;

    cudaFuncSetAttribute(k_gemm1, cudaFuncAttributeMaxDynamicSharedMemorySize, SMEM_SZ);
    cudaFuncSetAttribute(k_gemm2, cudaFuncAttributeMaxDynamicSharedMemorySize, SMEM_SZ);

    k_zero<<<4096, 256>>>(out, (size_t)BL * H_ / 4);
    k_conv_gu<<<64 * 172, 256>>>(gw, uw);
    k_conv_down<<<64 * 172, 256>>>(dw);
    k_rmsnorm<<<BL, 256>>>(x, mk, lnw);
    k_gemm1<<<8 * 43 * 16, 256, SMEM_SZ>>>(gb, ub);
    k_gemm2<<<8 * 8 * 16, 256, SMEM_SZ>>>(db, out);
}

// round 6
// speedup vs baseline: 4.5600x; 1.0095x over previous
#include <cuda_runtime.h>
#include <cuda_fp16.h>
#include <cstdint>

#define B_  4
#define L_  4096
#define H_  2048
#define I_  5504
#define BL  16384           // B_*L_
#define I2  11008           // 2*I_

// ---------------- scratch (device globals; no allocation allowed) ----------------
__device__ __align__(256) __half g_h[(size_t)BL * H_];       // [slot][H_] fp16
__device__ __align__(256) __half g_act[(size_t)BL * I_];     // [slot][I_] fp16
__device__ __align__(256) __half g_wgu[(size_t)I2 * H_];     // [n][k], n interleaved (gate,up)
__device__ __align__(256) __half g_wd[(size_t)H_ * I_];      // [n=h][k=i]
__device__ int g_idx[BL];
__device__ int g_count;

// ---------------- helpers ----------------
__device__ __forceinline__ uint32_t smem_u32(const void* p) {
    return (uint32_t)__cvta_generic_to_shared(p);
}
#define SWZ128(off) ((off) ^ (((off) >> 3) & 0x70))

__device__ __forceinline__ void ldm4(uint32_t* r, uint32_t addr) {
    asm volatile("ldmatrix.sync.aligned.m8n8.x4.shared.b16 {%0,%1,%2,%3}, [%4];"
                 : "=r"(r[0]), "=r"(r[1]), "=r"(r[2]), "=r"(r[3]) : "r"(addr));
}
__device__ __forceinline__ void mma_f16(float* c, const uint32_t* a, const uint32_t* b) {
    asm volatile("mma.sync.aligned.m16n8k16.row.col.f32.f16.f16.f32 "
                 "{%0,%1,%2,%3}, {%4,%5,%6,%7}, {%8,%9}, {%0,%1,%2,%3};"
                 : "+f"(c[0]), "+f"(c[1]), "+f"(c[2]), "+f"(c[3])
                 : "r"(a[0]), "r"(a[1]), "r"(a[2]), "r"(a[3]), "r"(b[0]), "r"(b[1]));
}

// ---------------- kernel: zero output + reset counter ----------------
__global__ void k_zero(float* __restrict__ out, size_t n4) {
    size_t i = (size_t)blockIdx.x * blockDim.x + threadIdx.x;
    size_t stride = (size_t)gridDim.x * blockDim.x;
    float4 z = make_float4(0.f, 0.f, 0.f, 0.f);
    float4* o4 = reinterpret_cast<float4*>(out);
    for (; i < n4; i += stride) o4[i] = z;
    if (blockIdx.x == 0 && threadIdx.x == 0) g_count = 0;
}

// ---------------- conversion: transpose gate/up -> wgu[n][k] fp16, n interleaved ----------------
__global__ void k_conv_gu(const float* __restrict__ gw, const float* __restrict__ uw) {
    __shared__ float sg[32][33], su[32][33];
    int bid = blockIdx.x;
    int kt0 = (bid & 63) << 5;        // 64 k-tiles over H_
    int jt0 = (bid >> 6) << 5;        // 172 j-tiles over I_
    int tid = threadIdx.x;
#pragma unroll
    for (int i = 0; i < 4; i++) {
        int idx = tid + (i << 8);
        int r = idx >> 5, c = idx & 31;
        size_t src = (size_t)(kt0 + r) * I_ + jt0 + c;
        sg[r][c] = gw[src];
        su[r][c] = uw[src];
    }
    __syncthreads();
#pragma unroll
    for (int i = 0; i < 4; i++) {
        int idx = tid + (i << 8);
        int jr = idx >> 5, kc = idx & 31;
        size_t og = (size_t)((jt0 + jr) << 1) * H_ + kt0 + kc;
        g_wgu[og]      = __float2half(sg[kc][jr]);
        g_wgu[og + H_] = __float2half(su[kc][jr]);
    }
}

// down_w [I_][H_] -> wd[n=h][k=i] fp16
__global__ void k_conv_down(const float* __restrict__ dw) {
    __shared__ float s[32][33];
    int bid = blockIdx.x;
    int ht0 = (bid & 63) << 5;
    int it0 = (bid >> 6) << 5;
    int tid = threadIdx.x;
#pragma unroll
    for (int i = 0; i < 4; i++) {
        int idx = tid + (i << 8);
        int r = idx >> 5, c = idx & 31;
        s[r][c] = dw[(size_t)(it0 + r) * H_ + ht0 + c];
    }
    __syncthreads();
#pragma unroll
    for (int i = 0; i < 4; i++) {
        int idx = tid + (i << 8);
        int hr = idx >> 5, ic = idx & 31;
        g_wd[(size_t)(ht0 + hr) * I_ + it0 + ic] = __float2half(s[ic][hr]);
    }
}

// ---------------- RMSNorm + mask compaction (mask is int32) ----------------
__global__ void k_rmsnorm(const float* __restrict__ x,
                          const int* __restrict__ mask,
                          const float* __restrict__ lnw) {
    int token = blockIdx.x;
    if (mask[token] == 0) return;              // masked tokens: no work at all
    int tid = threadIdx.x;
    const float4* row = reinterpret_cast<const float4*>(x + (size_t)token * H_);
    float4 v[2];
    float ss = 0.f;
#pragma unroll
    for (int i = 0; i < 2; i++) {
        float4 t = row[tid + i * 256];
        v[i] = t;
        ss += t.x * t.x + t.y * t.y + t.z * t.z + t.w * t.w;
    }
#pragma unroll
    for (int o = 16; o > 0; o >>= 1) ss += __shfl_xor_sync(0xffffffffu, ss, o);

    __shared__ float warpsum[8];
    __shared__ float s_rs;
    __shared__ int s_slot;
    if ((tid & 31) == 0) warpsum[tid >> 5] = ss;
    __syncthreads();
    if (tid == 0) {
        float tot = 0.f;
#pragma unroll
        for (int w = 0; w < 8; w++) tot += warpsum[w];
        s_rs = rsqrtf(tot * (1.0f / H_) + 1e-6f);
        int slot = atomicAdd(&g_count, 1);
        s_slot = slot;
        g_idx[slot] = token;
    }
    __syncthreads();
    int slot = s_slot;
    float rs = s_rs;

    const float4* lw4 = reinterpret_cast<const float4*>(lnw);
#pragma unroll
    for (int i = 0; i < 2; i++) {
        int c4 = tid + i * 256;
        float4 w = lw4[c4];
        __half2* ph = reinterpret_cast<__half2*>(g_h + (size_t)slot * H_ + (size_t)c4 * 4);
        ph[0] = __halves2half2(__float2half(v[i].x * rs * w.x),
                               __float2half(v[i].y * rs * w.y));
        ph[1] = __halves2half2(__float2half(v[i].z * rs * w.z),
                               __float2half(v[i].w * rs * w.w));
    }
}

// ---------------- GEMM core: CTA 128x256, TK=64, 4-stage cp.async pipeline ----------------
// buffer (48KB): A [128][64] @0 (16KB), B [256][64] @16K (32KB). 4 buffers = 192KB.
// Register-double-buffered ldmatrix fragments hide LDS latency under MMA issue.
#define BUFSZ 49152
#define NSTAGE 4
#define SMEM_SZ (NSTAGE * BUFSZ)

__device__ __forceinline__ void load_chunk(uint32_t smb, int buf,
    const __half* __restrict__ Ap, long ldA,
    const __half* __restrict__ Bp, long ldB, int k0, int tid)
{
    uint32_t sA = smb + buf * BUFSZ;
    uint32_t sB = sA + 16384;
#pragma unroll
    for (int i = 0; i < 4; i++) {               // A: 128 rows x 128B
        int u = tid + (i << 8);
        int row = u >> 3, seg = u & 7;
        const void* g = Ap + (long)row * ldA + k0 + (seg << 3);
        asm volatile("cp.async.cg.shared.global [%0], [%1], 16;"
                     :: "r"(sA + SWZ128((row << 7) + (seg << 4))), "l"(g));
    }
#pragma unroll
    for (int i = 0; i < 8; i++) {               // B: 256 rows x 128B
        int u = tid + (i << 8);
        int row = u >> 3, seg = u & 7;
        const void* g = Bp + (long)row * ldB + k0 + (seg << 3);
        asm volatile("cp.async.cg.shared.global [%0], [%1], 16;"
                     :: "r"(sB + SWZ128((row << 7) + (seg << 4))), "l"(g));
    }
}

__device__ __forceinline__ void frag_load(uint32_t sA, uint32_t sB, int ks,
    int arow, int akh, int brow, int bkh,
    uint32_t a[4][4], uint32_t b[8][2])
{
#pragma unroll
    for (int q = 0; q < 4; q++)
        ldm4(&b[2 * q][0], sB + SWZ128(((brow + q * 16) << 7) + ks * 32 + bkh));
#pragma unroll
    for (int mf = 0; mf < 4; mf++)
        ldm4(a[mf], sA + SWZ128(((arow + mf * 16) << 7) + ks * 32 + akh));
}

__device__ __forceinline__ void gemm_main(uint32_t smb,
    const __half* Ap, long ldA, const __half* Bp, long ldB, int nch,
    float c[4][8][4], int tid, int wm, int wn, int lane)
{
    int arow = wm * 64 + (lane & 15);
    int akh  = (lane >> 4) << 4;
    int brow = wn * 64 + ((lane >> 4) << 3) + (lane & 7);
    int bkh  = ((lane >> 3) & 1) << 4;

#pragma unroll
    for (int p = 0; p < NSTAGE - 1; p++) {
        load_chunk(smb, p, Ap, ldA, Bp, ldB, p * 64, tid);
        asm volatile("cp.async.commit_group;" ::: "memory");
    }

    uint32_t a[2][4][4], b[2][8][2];
    int cbuf = 0, ldbuf = NSTAGE - 1;
#pragma unroll 1
    for (int ch = 0; ch < nch; ch++) {
        asm volatile("cp.async.wait_group %0;" :: "n"(NSTAGE - 2) : "memory");
        __syncthreads();   // all warps done with buffer (ch-1)%N before overwrite
        if (ch + NSTAGE - 1 < nch)
            load_chunk(smb, ldbuf, Ap, ldA, Bp, ldB, (ch + NSTAGE - 1) * 64, tid);
        asm volatile("cp.async.commit_group;" ::: "memory");

        uint32_t sA = smb + cbuf * BUFSZ;
        uint32_t sB = sA + 16384;
        frag_load(sA, sB, 0, arow, akh, brow, bkh, a[0], b[0]);
#pragma unroll
        for (int ks = 0; ks < 4; ks++) {
            if (ks < 3)
                frag_load(sA, sB, ks + 1, arow, akh, brow, bkh,
                          a[(ks + 1) & 1], b[(ks + 1) & 1]);
            uint32_t (*ac)[4] = a[ks & 1];
            uint32_t (*bc)[2] = b[ks & 1];
#pragma unroll
            for (int mf = 0; mf < 4; mf++)
#pragma unroll
                for (int q = 0; q < 8; q++) mma_f16(c[mf][q], ac[mf], bc[q]);
        }
        if (++ldbuf == NSTAGE) ldbuf = 0;
        if (++cbuf == NSTAGE) cbuf = 0;
    }
}

// ---------------- GEMM1: h[M,2048] x wgu[11008,2048]^T, epilogue silu(g)*u ----------------
// grid: 8 m-supertiles x 43 n x 16 m  (m fastest for L2 reuse of B)
__global__ __launch_bounds__(256, 1) void k_gemm1(const float* __restrict__ gate_b,
                                                  const float* __restrict__ up_b) {
    extern __shared__ __align__(128) char sm[];
    int cnt = g_count;
    int bid = blockIdx.x;
    int mi = bid & 15, nt = (bid >> 4) % 43, ms = bid / 688;
    int m_base = (ms * 16 + mi) << 7;
    if (m_base >= cnt) return;
    int n_base = nt << 8;
    int tid = threadIdx.x, lane = tid & 31, w = tid >> 5, wm = w >> 2, wn = w & 3;

    float c[4][8][4];
#pragma unroll
    for (int mf = 0; mf < 4; mf++)
#pragma unroll
        for (int q = 0; q < 8; q++)
#pragma unroll
            for (int i = 0; i < 4; i++) c[mf][q][i] = 0.f;

    gemm_main(smem_u32(sm), g_h + (size_t)m_base * H_, H_,
              g_wgu + (size_t)n_base * H_, H_, H_ / 64, c, tid, wm, wn, lane);

    int jb = (n_base >> 1) + wn * 32 + (lane & 3);
    float bg[8], bu[8];
#pragma unroll
    for (int q = 0; q < 8; q++) { bg[q] = gate_b[jb + q * 4]; bu[q] = up_b[jb + q * 4]; }
#pragma unroll
    for (int mf = 0; mf < 4; mf++) {
#pragma unroll
        for (int rr = 0; rr < 2; rr++) {
            int row = m_base + wm * 64 + mf * 16 + (lane >> 2) + rr * 8;
            if (row < cnt) {
#pragma unroll
                for (int q = 0; q < 8; q++) {
                    float gg = c[mf][q][rr * 2 + 0] + bg[q];
                    float uu = c[mf][q][rr * 2 + 1] + bu[q];
                    float act = gg / (1.f + __expf(-gg)) * uu;
                    g_act[(size_t)row * I_ + jb + q * 4] = __float2half(act);
                }
            }
        }
    }
}

// ---------------- GEMM2: act[M,5504] x wd[2048,5504]^T, scatter + bias ----------------
// grid: 8 m-supertiles x 8 n x 16 m
__global__ __launch_bounds__(256, 1) void k_gemm2(const float* __restrict__ down_b,
                                                  float* __restrict__ out) {
    extern __shared__ __align__(128) char sm[];
    int cnt = g_count;
    int bid = blockIdx.x;
    int mi = bid & 15, nt = (bid >> 4) & 7, ms = bid >> 7;
    int m_base = (ms * 16 + mi) << 7;
    if (m_base >= cnt) return;
    int n_base = nt << 8;
    int tid = threadIdx.x, lane = tid & 31, w = tid >> 5, wm = w >> 2, wn = w & 3;

    float c[4][8][4];
#pragma unroll
    for (int mf = 0; mf < 4; mf++)
#pragma unroll
        for (int q = 0; q < 8; q++)
#pragma unroll
            for (int i = 0; i < 4; i++) c[mf][q][i] = 0.f;

    gemm_main(smem_u32(sm), g_act + (size_t)m_base * I_, I_,
              g_wd + (size_t)n_base * I_, I_, I_ / 64, c, tid, wm, wn, lane);

    int nb = n_base + wn * 64 + (lane & 3) * 2;
    float d0[8], d1[8];
#pragma unroll
    for (int q = 0; q < 8; q++) { d0[q] = down_b[nb + q * 8]; d1[q] = down_b[nb + q * 8 + 1]; }
#pragma unroll
    for (int mf = 0; mf < 4; mf++) {
#pragma unroll
        for (int rr = 0; rr < 2; rr++) {
            int row = m_base + wm * 64 + mf * 16 + (lane >> 2) + rr * 8;
            if (row < cnt) {
                int token = g_idx[row];
                float* orow = out + (size_t)token * H_;
#pragma unroll
                for (int q = 0; q < 8; q++) {
                    float2 v = make_float2(c[mf][q][rr * 2 + 0] + d0[q],
                                           c[mf][q][rr * 2 + 1] + d1[q]);
                    *reinterpret_cast<float2*>(orow + nb + q * 8) = v;
                }
            }
        }
    }
}

// ---------------- launch ----------------
extern "C" void kernel_launch(void* const* d_in, const int* in_sizes, int n_in,
                              void* d_out, int out_size) {
    (void)in_sizes; (void)n_in; (void)out_size;
    const float* x   = (const float*)d_in[0];
    const int* mk    = (const int*)d_in[1];
    const float* lnw = (const float*)d_in[2];
    const float* gw  = (const float*)d_in[3];
    const float* gb  = (const float*)d_in[4];
    const float* uw  = (const float*)d_in[5];
    const float* ub  = (const float*)d_in[6];
    const float* dw  = (const float*)d_in[7];
    const float* db  = (const float*)d_in[8];
    float* out = (float*)d_out;

    cudaFuncSetAttribute(k_gemm1, cudaFuncAttributeMaxDynamicSharedMemorySize, SMEM_SZ);
    cudaFuncSetAttribute(k_gemm2, cudaFuncAttributeMaxDynamicSharedMemorySize, SMEM_SZ);

    k_zero<<<4096, 256>>>(out, (size_t)BL * H_ / 4);
    k_conv_gu<<<64 * 172, 256>>>(gw, uw);
    k_conv_down<<<64 * 172, 256>>>(dw);
    k_rmsnorm<<<BL, 256>>>(x, mk, lnw);
    k_gemm1<<<8 * 43 * 16, 256, SMEM_SZ>>>(gb, ub);
    k_gemm2<<<8 * 8 * 16, 256, SMEM_SZ>>>(db, out);
}